// round 3
// baseline (speedup 1.0000x reference)
#include <cuda_runtime.h>

#define PI_F 3.14159265358979f

typedef unsigned long long u64;

// ---------- packed f32x2 helpers (sm_103a) ----------
__device__ __forceinline__ u64 pk(float a, float b) {
    u64 r; asm("mov.b64 %0,{%1,%2};" : "=l"(r) : "f"(a), "f"(b)); return r;
}
__device__ __forceinline__ void upk(u64 x, float& a, float& b) {
    asm("mov.b64 {%0,%1},%2;" : "=f"(a), "=f"(b) : "l"(x));
}
#define FMA2(d,a,b,c) asm("fma.rn.f32x2 %0,%1,%2,%3;" : "=l"(d) : "l"(a), "l"(b), "l"(c))
#define MUL2(d,a,b)   asm("mul.rn.f32x2 %0,%1,%2;"    : "=l"(d) : "l"(a), "l"(b))
#define ADD2(d,a,b)   asm("add.rn.f32x2 %0,%1,%2;"    : "=l"(d) : "l"(a), "l"(b))

// Packed (duplicated-pair) parameters, precomputed per block by thread 0.
struct PParams {
    u64 ROUGH;                  // roughness
    u64 INVAX2, INVAY2;         // 1/ax^2, 1/ay^2
    u64 AX2, AY2;               // ax^2, ay^2
    u64 A2M1;                   // a_cc^2 - 1
    u64 S1, S2, S3, S4;         // 1-sub, 1.25*sub, -0.625*sub, 0.625*sub
    u64 KA, KB;                 // 0.04*(0.25*cc*dr_k), 0.96*(0.25*cc*dr_k)
    u64 CS0, CS1, CS2;          // c_spec0 / (pi*ax*ay)
    u64 ICS0, ICS1, ICS2;       // (1 - c_spec0) / (pi*ax*ay)
    u64 SHN0, SHN1, SHN2;       // sheen color premult
    u64 DIF0, DIF1, DIF2;       // (1-mtl)/pi * cd_lin
};

__device__ __forceinline__ float lerpf(float a, float b, float w) { return a + w * (b - a); }

__device__ __forceinline__ void compute_params(PParams* sp,
        const float* __restrict__ base_color, const float* __restrict__ metallic,
        const float* __restrict__ subsurface, const float* __restrict__ specular,
        const float* __restrict__ roughness, const float* __restrict__ specular_tint,
        const float* __restrict__ anisotropic, const float* __restrict__ sheen,
        const float* __restrict__ sheen_tint, const float* __restrict__ clear_coat,
        const float* __restrict__ clear_coat_gloss) {
    float mtl = metallic[0];
    float sub = subsurface[0];
    float spec = specular[0];
    float rough = roughness[0];
    float sp_tint = specular_tint[0];
    float aniso = anisotropic[0];
    float sh = sheen[0];
    float sh_tint = sheen_tint[0];
    float cc = clear_coat[0];
    float ccg = clear_coat_gloss[0];

    float cd[3];
    #pragma unroll
    for (int i = 0; i < 3; i++) cd[i] = powf(base_color[i], 2.2f);
    float lum = 0.3f * cd[0] + 0.6f * cd[1] + 0.1f * cd[2];
    float ct[3];
    #pragma unroll
    for (int i = 0; i < 3; i++)
        ct[i] = (lum > 0.0f) ? cd[i] / fmaxf(lum, 1e-20f) : 0.0f;

    float aspect = sqrtf(1.0f - aniso * 0.9f);
    float r2 = rough * rough;
    float ax = fmaxf(0.001f, r2 / aspect);
    float ay = fmaxf(0.001f, r2 * aspect);
    float inv_piaxay = 1.0f / (PI_F * ax * ay);

    float a_cc = lerpf(0.1f, 0.001f, ccg);
    float a2 = a_cc * a_cc;
    float a2m1, dr_k;
    if (a_cc >= 1.0f) { a2m1 = 0.0f; dr_k = 1.0f / PI_F; }
    else { a2m1 = a2 - 1.0f; dr_k = (a2 - 1.0f) / (PI_F * logf(a2)); }
    float ccdrk = 0.25f * cc * dr_k;

    sp->ROUGH  = pk(rough, rough);
    sp->INVAX2 = pk(1.0f / (ax * ax), 1.0f / (ax * ax));
    sp->INVAY2 = pk(1.0f / (ay * ay), 1.0f / (ay * ay));
    sp->AX2    = pk(ax * ax, ax * ax);
    sp->AY2    = pk(ay * ay, ay * ay);
    sp->A2M1   = pk(a2m1, a2m1);
    sp->S1     = pk(1.0f - sub, 1.0f - sub);
    sp->S2     = pk(1.25f * sub, 1.25f * sub);
    sp->S3     = pk(-0.625f * sub, -0.625f * sub);
    sp->S4     = pk(0.625f * sub, 0.625f * sub);
    sp->KA     = pk(0.04f * ccdrk, 0.04f * ccdrk);
    sp->KB     = pk(0.96f * ccdrk, 0.96f * ccdrk);

    float cs[3];
    u64* CS  = &sp->CS0;
    u64* ICS = &sp->ICS0;
    u64* SHN = &sp->SHN0;
    u64* DIF = &sp->DIF0;
    #pragma unroll
    for (int i = 0; i < 3; i++) {
        cs[i] = lerpf(spec * 0.08f * lerpf(1.0f, ct[i], sp_tint), cd[i], mtl);
        float csk  = cs[i] * inv_piaxay;
        float icsk = (1.0f - cs[i]) * inv_piaxay;
        float shn  = sh * (1.0f - mtl) * lerpf(1.0f, ct[i], sh_tint);
        float dif  = (1.0f - mtl) * (1.0f / PI_F) * cd[i];
        CS[i]  = pk(csk, csk);
        ICS[i] = pk(icsk, icsk);
        SHN[i] = pk(shn, shn);
        DIF[i] = pk(dif, dif);
    }
}

// Process TWO elements with packed f32x2 math. MUFU ops stay scalar.
__device__ __forceinline__ void brdf_pair(const PParams& q,
        float lx0, float ly0, float lz0, float vx0, float vy0, float vz0,
        float lx1, float ly1, float lz1, float vx1, float vy1, float vz1,
        float* o0, float* o1) {
    const u64 ONE  = pk(1.0f, 1.0f);
    const u64 NEG1 = pk(-1.0f, -1.0f);
    const u64 NHALF = pk(-0.5f, -0.5f);
    const u64 C9375 = pk(0.9375f, 0.9375f);
    const u64 C0625 = pk(0.0625f, 0.0625f);

    u64 LX = pk(lx0, lx1), LY = pk(ly0, ly1), LZ = pk(lz0, lz1);
    u64 VX = pk(vx0, vx1), VY = pk(vy0, vy1), VZ = pk(vz0, vz1);

    u64 HX, HY, HZ;
    ADD2(HX, LX, VX); ADD2(HY, LY, VY); ADD2(HZ, LZ, VZ);
    u64 N2;
    MUL2(N2, HX, HX); FMA2(N2, HY, HY, N2); FMA2(N2, HZ, HZ, N2);
    float n0, n1; upk(N2, n0, n1);
    u64 INVH = pk(rsqrtf(n0), rsqrtf(n1));
    MUL2(HX, HX, INVH); MUL2(HY, HY, INVH); MUL2(HZ, HZ, INVH);

    u64 CHL;
    MUL2(CHL, HX, LX); FMA2(CHL, HY, LY, CHL); FMA2(CHL, HZ, LZ, CHL);

    bool v0 = (lz0 >= 0.0f) && (vz0 >= 0.0f);
    bool v1 = (lz1 >= 0.0f) && (vz1 >= 0.0f);
    float cnl0 = v0 ? lz0 : 0.5f, cnv0 = v0 ? vz0 : 0.5f;
    float cnl1 = v1 ? lz1 : 0.5f, cnv1 = v1 ? vz1 : 0.5f;
    u64 CNL = pk(cnl0, cnl1), CNV = pk(cnv0, cnv1);

    // schlick powers: m = 1 - u ; f = m^5  (no clamp needed: u in [0, 1+ulp])
    u64 ML, MV, MH, T, FL, FV, FH;
    FMA2(ML, CNL, NEG1, ONE);
    FMA2(MV, CNV, NEG1, ONE);
    FMA2(MH, CHL, NEG1, ONE);
    MUL2(T, ML, ML); MUL2(T, T, T); MUL2(FL, T, ML);
    MUL2(T, MV, MV); MUL2(T, T, T); MUL2(FV, T, MV);
    MUL2(T, MH, MH); MUL2(T, T, T); MUL2(FH, T, MH);

    u64 C2R;
    MUL2(C2R, CHL, CHL); MUL2(C2R, C2R, q.ROUGH);

    // fd = (1 + (2*c2r-0.5)*fl) * (1 + (2*c2r-0.5)*fv)
    u64 FD90, FD, T2;
    ADD2(FD90, C2R, C2R); ADD2(FD90, FD90, NHALF);
    FMA2(FD, FD90, FL, ONE); FMA2(T2, FD90, FV, ONE); MUL2(FD, FD, T2);
    // fss = (1 + (c2r-1)*fl) * (1 + (c2r-1)*fv)
    u64 FSSM1, FSS;
    ADD2(FSSM1, C2R, NEG1);
    FMA2(FSS, FSSM1, FL, ONE); FMA2(T2, FSSM1, FV, ONE); MUL2(FSS, FSS, T2);

    // rc = 1/(cnl+cnv)
    u64 CSUM; ADD2(CSUM, CNL, CNV);
    float cs0, cs1; upk(CSUM, cs0, cs1);
    u64 RC = pk(__fdividef(1.0f, cs0), __fdividef(1.0f, cs1));

    // dm = fd*(1-sub) + 1.25*sub*fss*rc - 0.625*sub*fss + 0.625*sub
    u64 DM;
    FMA2(DM, FSS, q.S3, q.S4);
    MUL2(T2, FSS, RC);
    FMA2(DM, T2, q.S2, DM);
    FMA2(DM, FD, q.S1, DM);

    // Ds denom (pi*ax*ay folded into CS/ICS): d = hx²/ax² + hy²/ay² + cnh² ; ds = d²
    u64 HX2, HY2, CNH2, D, DS;
    MUL2(HX2, HX, HX); MUL2(HY2, HY, HY); MUL2(CNH2, HZ, HZ);
    FMA2(D, HY2, q.INVAY2, CNH2);
    FMA2(D, HX2, q.INVAX2, D);
    MUL2(DS, D, D);

    // smith G aniso
    u64 CNL2, CNV2, SA, SV;
    MUL2(CNL2, CNL, CNL); MUL2(CNV2, CNV, CNV);
    MUL2(T, LY, LY); FMA2(SA, T, q.AY2, CNL2);
    MUL2(T, LX, LX); FMA2(SA, T, q.AX2, SA);
    MUL2(T, VY, VY); FMA2(SV, T, q.AY2, CNV2);
    MUL2(T, VX, VX); FMA2(SV, T, q.AX2, SV);
    float sa0, sa1, sv0, sv1;
    upk(SA, sa0, sa1); upk(SV, sv0, sv1);
    u64 RSA = pk(rsqrtf(sa0), rsqrtf(sa1));
    u64 RSV = pk(rsqrtf(sv0), rsqrtf(sv1));
    u64 AS, AV;
    FMA2(AS, SA, RSA, CNL);
    FMA2(AV, SV, RSV, CNV);

    u64 G;
    MUL2(G, DS, AS); MUL2(G, G, AV);
    float g0, g1; upk(G, g0, g1);
    u64 GSDS = pk(__fdividef(1.0f, g0), __fdividef(1.0f, g1));

    // clear coat
    u64 GA, GB;
    FMA2(GA, CNL2, C9375, C0625);
    FMA2(GB, CNV2, C9375, C0625);
    float ga0, ga1, gb0, gb1;
    upk(GA, ga0, ga1); upk(GB, gb0, gb1);
    u64 RGA = pk(rsqrtf(ga0), rsqrtf(ga1));
    u64 RGB = pk(rsqrtf(gb0), rsqrtf(gb1));
    u64 BA, BB, BR, TT, TB;
    FMA2(BA, GA, RGA, CNL);
    FMA2(BB, GB, RGB, CNV);
    MUL2(BR, BA, BB);
    FMA2(TT, CNH2, q.A2M1, ONE);
    MUL2(TB, TT, BR);
    float tb0, tb1; upk(TB, tb0, tb1);
    u64 RTB = pk(__fdividef(1.0f, tb0), __fdividef(1.0f, tb1));
    u64 CLEAR;
    FMA2(T2, FH, q.KB, q.KA);
    MUL2(CLEAR, T2, RTB);

    // channels: r = dif*dm + FH*shn + GsDs*(cs + FH*ics) + clear
    const u64* CS  = &q.CS0;
    const u64* ICS = &q.ICS0;
    const u64* SHN = &q.SHN0;
    const u64* DIF = &q.DIF0;
    #pragma unroll
    for (int c = 0; c < 3; c++) {
        u64 FS, R;
        FMA2(FS, FH, ICS[c], CS[c]);
        FMA2(R, DIF[c], DM, CLEAR);
        FMA2(R, FH, SHN[c], R);
        FMA2(R, GSDS, FS, R);
        float r0, r1; upk(R, r0, r1);
        o0[c] = v0 ? r0 : 0.0f;
        o1[c] = v1 ? r1 : 0.0f;
    }
}

#define SCALAR_ARGS                                                            \
    const float* __restrict__ a_bc,  const float* __restrict__ a_mtl,          \
    const float* __restrict__ a_sub, const float* __restrict__ a_spec,         \
    const float* __restrict__ a_rgh, const float* __restrict__ a_spt,          \
    const float* __restrict__ a_ani, const float* __restrict__ a_shn,          \
    const float* __restrict__ a_sht, const float* __restrict__ a_cc,           \
    const float* __restrict__ a_ccg

#define SCALAR_PASS a_bc, a_mtl, a_sub, a_spec, a_rgh, a_spt, a_ani, a_shn, a_sht, a_cc, a_ccg

// 4 elements/thread = 2 packed pairs. 6 float4 in, 3 float4 out per thread.
__global__ void __launch_bounds__(256)
brdf_kernel_vec(const float4* __restrict__ in, float4* __restrict__ out,
                int nquad, SCALAR_ARGS) {
    __shared__ PParams sp;
    int tid = blockIdx.x * blockDim.x + threadIdx.x;
    bool active = tid < nquad;

    float4 L[6];
    if (active) {
        #pragma unroll
        for (int i = 0; i < 6; i++) L[i] = in[(size_t)tid * 6 + i];
    }

    if (threadIdx.x == 0) compute_params(&sp, SCALAR_PASS);
    __syncthreads();
    if (!active) return;

    float ib[24];
    #pragma unroll
    for (int i = 0; i < 6; i++) {
        ib[4 * i + 0] = L[i].x;
        ib[4 * i + 1] = L[i].y;
        ib[4 * i + 2] = L[i].z;
        ib[4 * i + 3] = L[i].w;
    }

    float ob[12];
    brdf_pair(sp,
              ib[0], ib[1], ib[2], ib[3], ib[4], ib[5],
              ib[6], ib[7], ib[8], ib[9], ib[10], ib[11],
              &ob[0], &ob[3]);
    brdf_pair(sp,
              ib[12], ib[13], ib[14], ib[15], ib[16], ib[17],
              ib[18], ib[19], ib[20], ib[21], ib[22], ib[23],
              &ob[6], &ob[9]);

    #pragma unroll
    for (int i = 0; i < 3; i++) {
        float4 o;
        o.x = ob[4 * i + 0];
        o.y = ob[4 * i + 1];
        o.z = ob[4 * i + 2];
        o.w = ob[4 * i + 3];
        __stcs(&out[(size_t)tid * 3 + i], o);
    }
}

// Scalar tail (elements [start, n)) — only used when n % 4 != 0.
__global__ void __launch_bounds__(128)
brdf_kernel_tail(const float* __restrict__ in, float* __restrict__ out,
                 int start, int n, SCALAR_ARGS) {
    __shared__ PParams sp;
    if (threadIdx.x == 0) compute_params(&sp, SCALAR_PASS);
    __syncthreads();
    int i = start + blockIdx.x * blockDim.x + threadIdx.x;
    if (i >= n) return;
    const float* p = in + (size_t)i * 6;
    float o0[3], o1[3];
    brdf_pair(sp, p[0], p[1], p[2], p[3], p[4], p[5],
                  p[0], p[1], p[2], p[3], p[4], p[5], o0, o1);
    out[(size_t)i * 3 + 0] = o0[0];
    out[(size_t)i * 3 + 1] = o0[1];
    out[(size_t)i * 3 + 2] = o0[2];
}

extern "C" void kernel_launch(void* const* d_in, const int* in_sizes, int n_in,
                              void* d_out, int out_size) {
    const float* inputs = (const float*)d_in[0];
    int n = in_sizes[0] / 6;

    const float* a_bc  = (const float*)d_in[1];
    const float* a_mtl = (const float*)d_in[2];
    const float* a_sub = (const float*)d_in[3];
    const float* a_spec= (const float*)d_in[4];
    const float* a_rgh = (const float*)d_in[5];
    const float* a_spt = (const float*)d_in[6];
    const float* a_ani = (const float*)d_in[7];
    const float* a_shn = (const float*)d_in[8];
    const float* a_sht = (const float*)d_in[9];
    const float* a_cc  = (const float*)d_in[10];
    const float* a_ccg = (const float*)d_in[11];

    int nquad = n / 4;
    if (nquad > 0) {
        int threads = 256;
        int blocks = (nquad + threads - 1) / threads;
        brdf_kernel_vec<<<blocks, threads>>>((const float4*)inputs,
                                             (float4*)d_out, nquad,
                                             SCALAR_PASS);
    }
    int rem = n - nquad * 4;
    if (rem > 0) {
        brdf_kernel_tail<<<(rem + 127) / 128, 128>>>(inputs, (float*)d_out,
                                                     nquad * 4, n, SCALAR_PASS);
    }
}